// round 14
// baseline (speedup 1.0000x reference)
#include <cuda_runtime.h>
#include <math.h>
#include <stdint.h>

#define NN     50000
#define NE     800000
#define EF     16
#define HID    64
#define NC     10
#define NPICK  4096
#define NSCB   196            // ceil(NN/256)
#define EPB    48             // edges per block in k_edge
#define EBLK   16667          // ceil(NE/EPB)

typedef unsigned long long ull;

// ---------------- scratch (static device globals; no allocation) ----------------
__device__ float  g_M[EF * 256];         // folded gate weights, swizzled [k][p(n)]
__device__ float  g_c[256];              // folded gate bias, swizzled [p(n)]
__device__ float4 g_gate[NE];            // 4 per-layer gates, edge-id order (k_edge out)
__device__ float4 g_gatep[NE];           // gates * dis[src], CSR-slot order (scatter out)
__device__ int    g_srcp[NE];            // CSR: source node per slot
__device__ float  g_deg[4 * NN];         // per-layer degree sums (atomic)
__device__ float4 g_dis4[NN];            // per-node rsqrt(deg_l+1), 4 layers packed
__device__ __align__(256) float g_h[NN * HID];    // h = x @ W (unscaled)
__device__ __align__(256) float g_xa[NN * HID];
__device__ __align__(256) float g_xb[NN * HID];
__device__ int    g_cnt[NN];
__device__ int    g_tmp[NN];
__device__ int    g_bsum[256];
__device__ int    g_boff[256];
__device__ int    g_rowptr[NN + 1];
__device__ int    g_pos[NN];

__device__ __forceinline__ int clampi(int v, int hi) {
    return v < 0 ? 0 : (v >= hi ? hi - 1 : v);
}
__device__ __forceinline__ ull pack2(float x) {
    ull r; unsigned int b = __float_as_uint(x);
    asm("mov.b64 %0, {%1, %2};" : "=l"(r) : "r"(b), "r"(b));
    return r;
}
__device__ __forceinline__ void fma2(ull& d, ull a, ull b) {
    asm("fma.rn.f32x2 %0, %1, %2, %0;" : "+l"(d) : "l"(a), "l"(b));
}
__device__ __forceinline__ void unpack2(ull v, float& lo, float& hi) {
    unsigned int l, h;
    asm("mov.b64 {%0, %1}, %2;" : "=r"(l), "=r"(h) : "l"(v));
    lo = __uint_as_float(l); hi = __uint_as_float(h);
}
// output-index swizzle for k_edge weights
__device__ __forceinline__ int swzn(int n) {
    int ng = n >> 3, i = n & 7;
    return (i < 4) ? (4 * ng + i) : (128 + 4 * ng + (i - 4));
}

// ---------------- weight folding: M = (encW1@encW2)@mlpW1, swizzled layout ----------------
__global__ __launch_bounds__(256) void k_fold(
    const float* __restrict__ encW1, const float* __restrict__ encb1,
    const float* __restrict__ encW2, const float* __restrict__ encb2,
    const float* __restrict__ mlpW1, const float* __restrict__ mlpb1)
{
    __shared__ float sW1[256], sW2[256], sWc[256], sbc[16];
    int tid = threadIdx.x;
    sW1[tid] = encW1[tid];
    sW2[tid] = encW2[tid];
    __syncthreads();
    {   // Wc = W1 @ W2 (16x16)
        int i = tid >> 4, j = tid & 15;
        float s = 0.f;
        #pragma unroll
        for (int k = 0; k < EF; k++) s += sW1[i * EF + k] * sW2[k * EF + j];
        sWc[tid] = s;
    }
    if (tid < EF) {
        float s = encb2[tid];
        #pragma unroll
        for (int k = 0; k < EF; k++) s += encb1[k] * sW2[k * EF + tid];
        sbc[tid] = s;
    }
    __syncthreads();
    #pragma unroll 1
    for (int m = 0; m < 16; m++) {
        int idx = tid + 256 * m;                 // 0..4095
        int l = idx >> 10, k = (idx >> 6) & 15, j = idx & 63;
        float s = 0.f;
        #pragma unroll
        for (int i = 0; i < EF; i++) s += sWc[k * EF + i] * mlpW1[(l * EF + i) * HID + j];
        g_M[k * 256 + swzn(l * 64 + j)] = s;
    }
    {
        int l = tid >> 6, j = tid & 63;
        float s = mlpb1[l * HID + j];
        #pragma unroll
        for (int i = 0; i < EF; i++) s += sbc[i] * mlpW1[(l * EF + i) * HID + j];
        g_c[swzn(tid)] = s;
    }
}

// ---------------- zero counters ----------------
__global__ void k_zero() {
    int i = blockIdx.x * blockDim.x + threadIdx.x;
    if (i < 4 * NN) g_deg[i] = 0.f;
    if (i < NN) g_cnt[i] = 0;
}

// ---------------- CSR build ----------------
__global__ void k_count(const int* __restrict__ colp) {
    int e = blockIdx.x * blockDim.x + threadIdx.x;
    if (e < NE) atomicAdd(&g_cnt[clampi(colp[e], NN)], 1);
}

// ---------------- h = x @ W (64x64, UNSCALED), warp per row, f32x2 ----------------
__global__ __launch_bounds__(256) void k_gemm(const float* __restrict__ xin,
                                              const float* __restrict__ W) {
    __shared__ __align__(16) float sWf[HID * HID];
    for (int i = threadIdx.x; i < HID * HID; i += 256) sWf[i] = W[i];
    __syncthreads();
    int w = (blockIdx.x * 256 + threadIdx.x) >> 5;
    int lane = threadIdx.x & 31;
    if (w >= NN) return;
    float2 xv = *(const float2*)&xin[(size_t)w * HID + lane * 2];
    const ull* sW = (const ull*)sWf;
    ull acc = 0;
    #pragma unroll
    for (int k = 0; k < HID; k++) {
        float xk = __shfl_sync(0xffffffffu, (k & 1) ? xv.y : xv.x, k >> 1);
        fma2(acc, pack2(xk), sW[k * 32 + lane]);
    }
    float lo, hi; unpack2(acc, lo, hi);
    *(float2*)&g_h[(size_t)w * HID + lane * 2] = make_float2(lo, hi);
}

// ---------------- tiled edge-gate GEMM: 48 edges x 256 outputs per block ----------------
__global__ __launch_bounds__(256, 3) void k_edge(const float* __restrict__ eattr,
                                                 const int* __restrict__ colp,
                                                 const float* __restrict__ mlpW2,
                                                 const float* __restrict__ mlpb2)
{
    __shared__ __align__(16) ull   sAp[EF][EPB];   // packed-dup edge values: 6 KB
    __shared__ __align__(16) float sW[EF * 256];   // swizzled folded M: 16 KB
    __shared__ __align__(16) float sC[256];        // swizzled folded bias
    __shared__ __align__(16) float sV[256];        // swizzled mlpW2
    __shared__ float sB[4];

    int tid = threadIdx.x;
    {   // weights: 16 KB straight copy (already swizzled by k_fold)
        const float4* src = (const float4*)g_M;
        float4* dst = (float4*)sW;
        #pragma unroll
        for (int i = 0; i < 4; i++) dst[tid + 256 * i] = src[tid + 256 * i];
    }
    sC[tid] = g_c[tid];
    sV[swzn(tid)] = mlpW2[tid];
    if (tid < 4) sB[tid] = mlpb2[tid];
    if (tid < 4 * EPB) {   // a-tile: 48 edges x 16 floats, packed+transposed
        int e = tid >> 2, q = tid & 3;
        int eglob = blockIdx.x * EPB + e;
        if (eglob >= NE) eglob = NE - 1;
        float4 v = ((const float4*)(eattr + (size_t)eglob * EF))[q];
        sAp[q * 4 + 0][e] = pack2(v.x);
        sAp[q * 4 + 1][e] = pack2(v.y);
        sAp[q * 4 + 2][e] = pack2(v.z);
        sAp[q * 4 + 3][e] = pack2(v.w);
    }
    __syncthreads();

    const int eg = tid >> 5;        // edges 6*eg .. 6*eg+5
    const int ng = tid & 31;
    const int pA = 4 * ng;          // swizzled chunk A
    const int pB = 128 + 4 * ng;    // swizzled chunk B

    ull accA[6][2], accB[6][2];
    {
        ulonglong2 cA = *(const ulonglong2*)&sC[pA];
        ulonglong2 cB = *(const ulonglong2*)&sC[pB];
        #pragma unroll
        for (int e = 0; e < 6; e++) {
            accA[e][0] = cA.x; accA[e][1] = cA.y;
            accB[e][0] = cB.x; accB[e][1] = cB.y;
        }
    }

    #pragma unroll
    for (int k = 0; k < EF; k++) {
        ulonglong2 wA = *(const ulonglong2*)&sW[k * 256 + pA];
        ulonglong2 wB = *(const ulonglong2*)&sW[k * 256 + pB];
        ulonglong2 a01 = *(const ulonglong2*)&sAp[k][eg * 6];
        ulonglong2 a23 = *(const ulonglong2*)&sAp[k][eg * 6 + 2];
        ulonglong2 a45 = *(const ulonglong2*)&sAp[k][eg * 6 + 4];
        ull av[6] = {a01.x, a01.y, a23.x, a23.y, a45.x, a45.y};
        #pragma unroll
        for (int e = 0; e < 6; e++) {
            fma2(accA[e][0], av[e], wA.x);
            fma2(accA[e][1], av[e], wA.y);
            fma2(accB[e][0], av[e], wB.x);
            fma2(accB[e][1], av[e], wB.y);
        }
    }

    float4 w2A = *(const float4*)&sV[pA];
    float4 w2B = *(const float4*)&sV[pB];
    float pz[6];
    #pragma unroll
    for (int e = 0; e < 6; e++) {
        float h0, h1, h2, h3, h4, h5, h6, h7;
        unpack2(accA[e][0], h0, h1); unpack2(accA[e][1], h2, h3);
        unpack2(accB[e][0], h4, h5); unpack2(accB[e][1], h6, h7);
        pz[e] = fmaxf(h0, 0.f) * w2A.x + fmaxf(h1, 0.f) * w2A.y
              + fmaxf(h2, 0.f) * w2A.z + fmaxf(h3, 0.f) * w2A.w
              + fmaxf(h4, 0.f) * w2B.x + fmaxf(h5, 0.f) * w2B.y
              + fmaxf(h6, 0.f) * w2B.z + fmaxf(h7, 0.f) * w2B.w;
    }
    #pragma unroll
    for (int off = 1; off < 8; off <<= 1) {
        #pragma unroll
        for (int e = 0; e < 6; e++)
            pz[e] += __shfl_xor_sync(0xffffffffu, pz[e], off);
    }
    if ((ng & 7) == 0) {
        int l = ng >> 3;
        float bl = sB[l];
        #pragma unroll
        for (int e = 0; e < 6; e++) {
            int eglob = blockIdx.x * EPB + eg * 6 + e;
            if (eglob < NE) {
                float g = 1.f / (1.f + __expf(-(pz[e] + bl)));
                ((float*)&g_gate[eglob])[l] = g;
                atomicAdd(&g_deg[l * NN + clampi(colp[eglob], NN)], g);
            }
        }
    }
}

// ---------------- dis4[n] = rsqrt(deg_l[n] + 1) packed per node ----------------
__global__ void k_dis4() {
    int i = blockIdx.x * blockDim.x + threadIdx.x;
    if (i < NN) {
        g_dis4[i] = make_float4(rsqrtf(g_deg[i] + 1.f),
                                rsqrtf(g_deg[NN + i] + 1.f),
                                rsqrtf(g_deg[2 * NN + i] + 1.f),
                                rsqrtf(g_deg[3 * NN + i] + 1.f));
    }
}

__global__ void k_scan1() {
    __shared__ int sh[256];
    int tid = threadIdx.x;
    int i = blockIdx.x * 256 + tid;
    int v = (i < NN) ? g_cnt[i] : 0;
    sh[tid] = v; __syncthreads();
    #pragma unroll
    for (int off = 1; off < 256; off <<= 1) {
        int t = (tid >= off) ? sh[tid - off] : 0;
        __syncthreads();
        sh[tid] += t;
        __syncthreads();
    }
    if (i < NN) g_tmp[i] = sh[tid] - v;
    if (tid == 255) g_bsum[blockIdx.x] = sh[255];
}

__global__ void k_scan2() {
    __shared__ int sh[256];
    int tid = threadIdx.x;
    int v = (tid < NSCB) ? g_bsum[tid] : 0;
    sh[tid] = v; __syncthreads();
    #pragma unroll
    for (int off = 1; off < 256; off <<= 1) {
        int t = (tid >= off) ? sh[tid - off] : 0;
        __syncthreads();
        sh[tid] += t;
        __syncthreads();
    }
    g_boff[tid] = sh[tid] - v;
}

__global__ void k_scan3() {
    int i = blockIdx.x * 256 + threadIdx.x;
    if (i < NN) {
        int r = g_tmp[i] + g_boff[blockIdx.x];
        g_rowptr[i] = r;
        g_pos[i] = r;
    }
    if (i == 0) g_rowptr[NN] = NE;
}

// ---------------- scatter + gate-prescale: gatep[p] = gate[e] * dis4[src] ----------------
__global__ void k_scatter(const int* __restrict__ rowp,
                          const int* __restrict__ colp) {
    int e = blockIdx.x * blockDim.x + threadIdx.x;
    if (e >= NE) return;
    int c = clampi(colp[e], NN);
    int s = clampi(rowp[e], NN);
    int p = atomicAdd(&g_pos[c], 1);
    p = clampi(p, NE);
    float4 d = g_dis4[s];               // random 16B gather
    float4 g = g_gate[e];               // sequential 16B
    g_srcp[p] = s;
    g_gatep[p] = make_float4(g.x * d.x, g.y * d.y, g.z * d.z, g.w * d.w);
}

// ---------------- SpMM (quarter-warp split): out = disc*(sum gp*h[src] + disc*h[c]) + b
// Quarter q = lane>>3 processes edges p = rs+q, rs+q+4, ...; lane li (0..7)
// covers floats [8*li, 8*li+8). Halves combined with f32x2 adds (fma2, NOT int +=).
__global__ __launch_bounds__(256) void k_spmm(const float* __restrict__ bias,
                                              float* __restrict__ xout,
                                              int l, int dorelu,
                                              const int* __restrict__ pick, int nrows) {
    int w = (blockIdx.x * blockDim.x + threadIdx.x) >> 5;
    int lane = threadIdx.x & 31;
    int q = lane >> 3;
    int li = lane & 7;
    if (w >= nrows) return;
    int c = pick ? clampi(pick[w], NN) : w;
    int rs = g_rowptr[c], re = g_rowptr[c + 1];
    ull a0 = 0, a1 = 0, a2 = 0, a3 = 0;
    #pragma unroll 2
    for (int p = rs + q; p < re; p += 4) {
        int s = g_srcp[p];
        float g = ((const float*)&g_gatep[p])[l];
        const ull* hp = (const ull*)&g_h[(size_t)s * HID + li * 8];
        ulonglong2 h01 = *(const ulonglong2*)hp;
        ulonglong2 h23 = *(const ulonglong2*)(hp + 2);
        ull gp = pack2(g);
        fma2(a0, gp, h01.x);
        fma2(a1, gp, h01.y);
        fma2(a2, gp, h23.x);
        fma2(a3, gp, h23.y);
    }
    float disc = ((const float*)&g_dis4[c])[l];
    {
        ull one = pack2(1.f);
        #pragma unroll
        for (int off = 8; off <= 16; off <<= 1) {
            ull t0 = __shfl_xor_sync(0xffffffffu, a0, off);
            ull t1 = __shfl_xor_sync(0xffffffffu, a1, off);
            ull t2 = __shfl_xor_sync(0xffffffffu, a2, off);
            ull t3 = __shfl_xor_sync(0xffffffffu, a3, off);
            fma2(a0, one, t0);
            fma2(a1, one, t1);
            fma2(a2, one, t2);
            fma2(a3, one, t3);
        }
        // self loop: + disc * h[c]
        ull dp = pack2(disc);
        const ull* hp = (const ull*)&g_h[(size_t)c * HID + li * 8];
        ulonglong2 h01 = *(const ulonglong2*)hp;
        ulonglong2 h23 = *(const ulonglong2*)(hp + 2);
        fma2(a0, dp, h01.x);
        fma2(a1, dp, h01.y);
        fma2(a2, dp, h23.x);
        fma2(a3, dp, h23.y);
    }
    if (q == 0) {
        float o[8];
        unpack2(a0, o[0], o[1]); unpack2(a1, o[2], o[3]);
        unpack2(a2, o[4], o[5]); unpack2(a3, o[6], o[7]);
        float4 b0 = *(const float4*)&bias[li * 8];
        float4 b1 = *(const float4*)&bias[li * 8 + 4];
        o[0] = o[0] * disc + b0.x; o[1] = o[1] * disc + b0.y;
        o[2] = o[2] * disc + b0.z; o[3] = o[3] * disc + b0.w;
        o[4] = o[4] * disc + b1.x; o[5] = o[5] * disc + b1.y;
        o[6] = o[6] * disc + b1.z; o[7] = o[7] * disc + b1.w;
        if (dorelu) {
            #pragma unroll
            for (int i = 0; i < 8; i++) o[i] = fmaxf(o[i], 0.f);
        }
        float* dst = &xout[(size_t)w * HID + li * 8];
        *(float4*)dst = make_float4(o[0], o[1], o[2], o[3]);
        *(float4*)(dst + 4) = make_float4(o[4], o[5], o[6], o[7]);
    }
}

// ---------------- classifier + softmax on compacted picked rows ----------------
__global__ __launch_bounds__(128) void k_final(const float* __restrict__ xin,
                                               const float* __restrict__ linW,
                                               const float* __restrict__ linb,
                                               float* __restrict__ out) {
    __shared__ float sW[HID * NC];
    __shared__ float sb[NC];
    for (int i = threadIdx.x; i < HID * NC; i += 128) sW[i] = linW[i];
    if (threadIdx.x < NC) sb[threadIdx.x] = linb[threadIdx.x];
    __syncthreads();
    int t = blockIdx.x * 128 + threadIdx.x;
    if (t >= NPICK) return;
    float lg[NC];
    #pragma unroll
    for (int j = 0; j < NC; j++) lg[j] = sb[j];
    const float4* xr = (const float4*)&xin[(size_t)t * HID];
    #pragma unroll
    for (int k4 = 0; k4 < 16; k4++) {
        float4 v = xr[k4];
        float xs[4] = {v.x, v.y, v.z, v.w};
        #pragma unroll
        for (int q = 0; q < 4; q++) {
            #pragma unroll
            for (int j = 0; j < NC; j++) lg[j] += xs[q] * sW[(k4 * 4 + q) * NC + j];
        }
    }
    float m = lg[0];
    #pragma unroll
    for (int j = 1; j < NC; j++) m = fmaxf(m, lg[j]);
    float ex[NC], s = 0.f;
    #pragma unroll
    for (int j = 0; j < NC; j++) { ex[j] = __expf(lg[j] - m); s += ex[j]; }
    float inv = 1.f / s;
    #pragma unroll
    for (int j = 0; j < NC; j++) out[(size_t)t * NC + j] = ex[j] * inv;
}

// ---------------- launch ----------------
extern "C" void kernel_launch(void* const* d_in, const int* in_sizes, int n_in,
                              void* d_out, int out_size) {
    const float* x      = (const float*)d_in[0];
    const float* eattr  = (const float*)d_in[1];
    const float* encW1  = (const float*)d_in[2];
    const float* encb1  = (const float*)d_in[3];
    const float* encW2  = (const float*)d_in[4];
    const float* encb2  = (const float*)d_in[5];
    const float* convW  = (const float*)d_in[6];
    const float* convB  = (const float*)d_in[7];
    const float* mlpW1  = (const float*)d_in[8];
    const float* mlpb1  = (const float*)d_in[9];
    const float* mlpW2  = (const float*)d_in[10];
    const float* mlpb2  = (const float*)d_in[11];
    const float* linW   = (const float*)d_in[12];
    const float* linb   = (const float*)d_in[13];
    const int* eidx     = (const int*)d_in[14];   // int32 (JAX x64 disabled)
    const int* pick     = (const int*)d_in[15];
    float* out = (float*)d_out;

    const int* rowp = eidx;
    const int* colp = eidx + NE;

    float *xa, *xb;
    cudaGetSymbolAddress((void**)&xa, g_xa);
    cudaGetSymbolAddress((void**)&xb, g_xb);

    const int EB = (NE + 255) / 256;        // 3125
    const int WB = (NN * 32 + 255) / 256;   // 6250
    const int PB = (NPICK * 32) / 256;      // 512

    // launch index 0..2
    k_fold<<<1, 256>>>(encW1, encb1, encW2, encb2, mlpW1, mlpb1);
    k_zero<<<(4 * NN + 255) / 256, 256>>>();
    k_count<<<EB, 256>>>(colp);

    // launch index 3: gemm layer 0 (unscaled; profiled by ncu window)
    k_gemm<<<WB, 256>>>(x, convW);

    // gates + degrees
    k_edge<<<EBLK, 256>>>(eattr, colp, mlpW2, mlpb2);
    k_dis4<<<(NN + 255) / 256, 256>>>();

    // CSR scan + scatter (scatter prescales gates by dis[src] and permutes)
    k_scan1<<<NSCB, 256>>>();
    k_scan2<<<1, 256>>>();
    k_scan3<<<NSCB, 256>>>();
    k_scatter<<<EB, 256>>>(rowp, colp);

    // layer 0 spmm, then layers 1-2, then picked layer 3
    float* bufs[2] = { xa, xb };
    k_spmm<<<WB, 256>>>(convB, bufs[0], 0, 1, (const int*)nullptr, NN);
    const float* xin = bufs[0];
    for (int l = 1; l < 3; l++) {
        k_gemm<<<WB, 256>>>(xin, convW + l * HID * HID);
        k_spmm<<<WB, 256>>>(convB + l * HID, bufs[l & 1], l, 1, (const int*)nullptr, NN);
        xin = bufs[l & 1];
    }
    k_gemm<<<WB, 256>>>(xin, convW + 3 * HID * HID);
    k_spmm<<<PB, 256>>>(convB + 3 * HID, xb, 3, 0, pick, NPICK);

    k_final<<<32, 128>>>(xb, linW, linb, out);
}

// round 16
// speedup vs baseline: 1.1962x; 1.1962x over previous
#include <cuda_runtime.h>
#include <math.h>
#include <stdint.h>

#define NN     50000
#define NE     800000
#define EF     16
#define HID    64
#define NC     10
#define NPICK  4096
#define NSCB   196            // ceil(NN/256)
#define EPB    48             // edges per block in k_edge
#define EBLK   16667          // ceil(NE/EPB)
#define GROWS  32             // rows per block in k_gemm
#define GBLK   1563           // ceil(NN/GROWS)

typedef unsigned long long ull;

// ---------------- scratch (static device globals; no allocation) ----------------
__device__ float  g_M[EF * 256];         // folded gate weights, swizzled [k][p(n)]
__device__ float  g_c[256];              // folded gate bias, swizzled [p(n)]
__device__ float4 g_gate[NE];            // 4 per-layer gates, edge-id order (k_edge out)
__device__ float4 g_gatep[NE];           // gates * dis[src], CSR-slot order (scatter out)
__device__ int    g_srcp[NE];            // CSR: source node per slot
__device__ float  g_deg[4 * NN];         // per-layer degree sums (atomic)
__device__ float4 g_dis4[NN];            // per-node rsqrt(deg_l+1), 4 layers packed
__device__ __align__(256) float g_h[NN * HID];    // h = x @ W (unscaled)
__device__ __align__(256) float g_xa[NN * HID];
__device__ __align__(256) float g_xb[NN * HID];
__device__ int    g_cnt[NN];
__device__ int    g_tmp[NN];
__device__ int    g_bsum[256];
__device__ int    g_boff[256];
__device__ int    g_rowptr[NN + 1];
__device__ int    g_pos[NN];

__device__ __forceinline__ int clampi(int v, int hi) {
    return v < 0 ? 0 : (v >= hi ? hi - 1 : v);
}
__device__ __forceinline__ ull pack2(float x) {
    ull r; unsigned int b = __float_as_uint(x);
    asm("mov.b64 %0, {%1, %2};" : "=l"(r) : "r"(b), "r"(b));
    return r;
}
__device__ __forceinline__ void fma2(ull& d, ull a, ull b) {
    asm("fma.rn.f32x2 %0, %1, %2, %0;" : "+l"(d) : "l"(a), "l"(b));
}
__device__ __forceinline__ void unpack2(ull v, float& lo, float& hi) {
    unsigned int l, h;
    asm("mov.b64 {%0, %1}, %2;" : "=r"(l), "=r"(h) : "l"(v));
    lo = __uint_as_float(l); hi = __uint_as_float(h);
}
// output-index swizzle for k_edge weights
__device__ __forceinline__ int swzn(int n) {
    int ng = n >> 3, i = n & 7;
    return (i < 4) ? (4 * ng + i) : (128 + 4 * ng + (i - 4));
}

// ---------------- weight folding: M = (encW1@encW2)@mlpW1, swizzled layout ----------------
__global__ __launch_bounds__(256) void k_fold(
    const float* __restrict__ encW1, const float* __restrict__ encb1,
    const float* __restrict__ encW2, const float* __restrict__ encb2,
    const float* __restrict__ mlpW1, const float* __restrict__ mlpb1)
{
    __shared__ float sW1[256], sW2[256], sWc[256], sbc[16];
    int tid = threadIdx.x;
    sW1[tid] = encW1[tid];
    sW2[tid] = encW2[tid];
    __syncthreads();
    {   // Wc = W1 @ W2 (16x16)
        int i = tid >> 4, j = tid & 15;
        float s = 0.f;
        #pragma unroll
        for (int k = 0; k < EF; k++) s += sW1[i * EF + k] * sW2[k * EF + j];
        sWc[tid] = s;
    }
    if (tid < EF) {
        float s = encb2[tid];
        #pragma unroll
        for (int k = 0; k < EF; k++) s += encb1[k] * sW2[k * EF + tid];
        sbc[tid] = s;
    }
    __syncthreads();
    #pragma unroll 1
    for (int m = 0; m < 16; m++) {
        int idx = tid + 256 * m;                 // 0..4095
        int l = idx >> 10, k = (idx >> 6) & 15, j = idx & 63;
        float s = 0.f;
        #pragma unroll
        for (int i = 0; i < EF; i++) s += sWc[k * EF + i] * mlpW1[(l * EF + i) * HID + j];
        g_M[k * 256 + swzn(l * 64 + j)] = s;
    }
    {
        int l = tid >> 6, j = tid & 63;
        float s = mlpb1[l * HID + j];
        #pragma unroll
        for (int i = 0; i < EF; i++) s += sbc[i] * mlpW1[(l * EF + i) * HID + j];
        g_c[swzn(tid)] = s;
    }
}

// ---------------- zero counters ----------------
__global__ void k_zero() {
    int i = blockIdx.x * blockDim.x + threadIdx.x;
    if (i < 4 * NN) g_deg[i] = 0.f;
    if (i < NN) g_cnt[i] = 0;
}

// ---------------- CSR build ----------------
__global__ void k_count(const int* __restrict__ colp) {
    int e = blockIdx.x * blockDim.x + threadIdx.x;
    if (e < NE) atomicAdd(&g_cnt[clampi(colp[e], NN)], 1);
}

// ---------------- h = x @ W, block-tiled: 32 rows x 64 cols, no shfl ----------------
// thread (eg = tid>>5, ng = tid&31): rows 4*eg..4*eg+3, cols 2*ng..2*ng+1 (one f32x2).
__global__ __launch_bounds__(256) void k_gemm(const float* __restrict__ xin,
                                              const float* __restrict__ W) {
    __shared__ __align__(16) ull sX[HID][GROWS];   // x transposed, packed-dup: 16 KB
    __shared__ __align__(16) ull sWp[HID * 32];    // W as natural f32x2 pairs: 16 KB
    int tid = threadIdx.x;
    {   // W copy: 4096 floats, contiguous pairs ARE the f32x2 operands
        const float4* src = (const float4*)W;
        float4* dst = (float4*)sWp;
        #pragma unroll
        for (int i = 0; i < 4; i++) dst[tid + 256 * i] = src[tid + 256 * i];
    }
    {   // x tile: 32 rows x 64 floats = 16 quads/row; each thread loads quads q and q+8
        int row = tid >> 3, q = tid & 7;
        int node = blockIdx.x * GROWS + row;
        if (node >= NN) node = NN - 1;
        const float4* xr = (const float4*)(xin + (size_t)node * HID);
        float4 v0 = xr[q];
        float4 v1 = xr[q + 8];
        sX[q * 4 + 0][row] = pack2(v0.x);
        sX[q * 4 + 1][row] = pack2(v0.y);
        sX[q * 4 + 2][row] = pack2(v0.z);
        sX[q * 4 + 3][row] = pack2(v0.w);
        sX[32 + q * 4 + 0][row] = pack2(v1.x);
        sX[32 + q * 4 + 1][row] = pack2(v1.y);
        sX[32 + q * 4 + 2][row] = pack2(v1.z);
        sX[32 + q * 4 + 3][row] = pack2(v1.w);
    }
    __syncthreads();

    int eg = tid >> 5;      // rows 4*eg .. 4*eg+3
    int ng = tid & 31;      // col pair ng
    ull acc0 = 0, acc1 = 0, acc2 = 0, acc3 = 0;
    #pragma unroll
    for (int k = 0; k < HID; k++) {
        ull wv = sWp[k * 32 + ng];                        // lane-contiguous LDS.64
        ulonglong2 x01 = *(const ulonglong2*)&sX[k][eg * 4];     // broadcast LDS.128
        ulonglong2 x23 = *(const ulonglong2*)&sX[k][eg * 4 + 2];
        fma2(acc0, x01.x, wv);
        fma2(acc1, x01.y, wv);
        fma2(acc2, x23.x, wv);
        fma2(acc3, x23.y, wv);
    }
    int base = blockIdx.x * GROWS + eg * 4;
    if (base + 0 < NN) *(ull*)&g_h[(size_t)(base + 0) * HID + 2 * ng] = acc0;
    if (base + 1 < NN) *(ull*)&g_h[(size_t)(base + 1) * HID + 2 * ng] = acc1;
    if (base + 2 < NN) *(ull*)&g_h[(size_t)(base + 2) * HID + 2 * ng] = acc2;
    if (base + 3 < NN) *(ull*)&g_h[(size_t)(base + 3) * HID + 2 * ng] = acc3;
}

// ---------------- tiled edge-gate GEMM: 48 edges x 256 outputs per block ----------------
__global__ __launch_bounds__(256, 3) void k_edge(const float* __restrict__ eattr,
                                                 const int* __restrict__ colp,
                                                 const float* __restrict__ mlpW2,
                                                 const float* __restrict__ mlpb2)
{
    __shared__ __align__(16) ull   sAp[EF][EPB];   // packed-dup edge values: 6 KB
    __shared__ __align__(16) float sW[EF * 256];   // swizzled folded M: 16 KB
    __shared__ __align__(16) float sC[256];        // swizzled folded bias
    __shared__ __align__(16) float sV[256];        // swizzled mlpW2
    __shared__ float sB[4];

    int tid = threadIdx.x;
    {   // weights: 16 KB straight copy (already swizzled by k_fold)
        const float4* src = (const float4*)g_M;
        float4* dst = (float4*)sW;
        #pragma unroll
        for (int i = 0; i < 4; i++) dst[tid + 256 * i] = src[tid + 256 * i];
    }
    sC[tid] = g_c[tid];
    sV[swzn(tid)] = mlpW2[tid];
    if (tid < 4) sB[tid] = mlpb2[tid];
    if (tid < 4 * EPB) {   // a-tile: 48 edges x 16 floats, packed+transposed
        int e = tid >> 2, q = tid & 3;
        int eglob = blockIdx.x * EPB + e;
        if (eglob >= NE) eglob = NE - 1;
        float4 v = ((const float4*)(eattr + (size_t)eglob * EF))[q];
        sAp[q * 4 + 0][e] = pack2(v.x);
        sAp[q * 4 + 1][e] = pack2(v.y);
        sAp[q * 4 + 2][e] = pack2(v.z);
        sAp[q * 4 + 3][e] = pack2(v.w);
    }
    __syncthreads();

    const int eg = tid >> 5;        // edges 6*eg .. 6*eg+5
    const int ng = tid & 31;
    const int pA = 4 * ng;          // swizzled chunk A
    const int pB = 128 + 4 * ng;    // swizzled chunk B

    ull accA[6][2], accB[6][2];
    {
        ulonglong2 cA = *(const ulonglong2*)&sC[pA];
        ulonglong2 cB = *(const ulonglong2*)&sC[pB];
        #pragma unroll
        for (int e = 0; e < 6; e++) {
            accA[e][0] = cA.x; accA[e][1] = cA.y;
            accB[e][0] = cB.x; accB[e][1] = cB.y;
        }
    }

    #pragma unroll
    for (int k = 0; k < EF; k++) {
        ulonglong2 wA = *(const ulonglong2*)&sW[k * 256 + pA];
        ulonglong2 wB = *(const ulonglong2*)&sW[k * 256 + pB];
        ulonglong2 a01 = *(const ulonglong2*)&sAp[k][eg * 6];
        ulonglong2 a23 = *(const ulonglong2*)&sAp[k][eg * 6 + 2];
        ulonglong2 a45 = *(const ulonglong2*)&sAp[k][eg * 6 + 4];
        ull av[6] = {a01.x, a01.y, a23.x, a23.y, a45.x, a45.y};
        #pragma unroll
        for (int e = 0; e < 6; e++) {
            fma2(accA[e][0], av[e], wA.x);
            fma2(accA[e][1], av[e], wA.y);
            fma2(accB[e][0], av[e], wB.x);
            fma2(accB[e][1], av[e], wB.y);
        }
    }

    float4 w2A = *(const float4*)&sV[pA];
    float4 w2B = *(const float4*)&sV[pB];
    float pz[6];
    #pragma unroll
    for (int e = 0; e < 6; e++) {
        float h0, h1, h2, h3, h4, h5, h6, h7;
        unpack2(accA[e][0], h0, h1); unpack2(accA[e][1], h2, h3);
        unpack2(accB[e][0], h4, h5); unpack2(accB[e][1], h6, h7);
        pz[e] = fmaxf(h0, 0.f) * w2A.x + fmaxf(h1, 0.f) * w2A.y
              + fmaxf(h2, 0.f) * w2A.z + fmaxf(h3, 0.f) * w2A.w
              + fmaxf(h4, 0.f) * w2B.x + fmaxf(h5, 0.f) * w2B.y
              + fmaxf(h6, 0.f) * w2B.z + fmaxf(h7, 0.f) * w2B.w;
    }
    #pragma unroll
    for (int off = 1; off < 8; off <<= 1) {
        #pragma unroll
        for (int e = 0; e < 6; e++)
            pz[e] += __shfl_xor_sync(0xffffffffu, pz[e], off);
    }
    if ((ng & 7) == 0) {
        int l = ng >> 3;
        float bl = sB[l];
        #pragma unroll
        for (int e = 0; e < 6; e++) {
            int eglob = blockIdx.x * EPB + eg * 6 + e;
            if (eglob < NE) {
                float g = 1.f / (1.f + __expf(-(pz[e] + bl)));
                ((float*)&g_gate[eglob])[l] = g;
                atomicAdd(&g_deg[l * NN + clampi(colp[eglob], NN)], g);
            }
        }
    }
}

// ---------------- dis4[n] = rsqrt(deg_l[n] + 1) packed per node ----------------
__global__ void k_dis4() {
    int i = blockIdx.x * blockDim.x + threadIdx.x;
    if (i < NN) {
        g_dis4[i] = make_float4(rsqrtf(g_deg[i] + 1.f),
                                rsqrtf(g_deg[NN + i] + 1.f),
                                rsqrtf(g_deg[2 * NN + i] + 1.f),
                                rsqrtf(g_deg[3 * NN + i] + 1.f));
    }
}

__global__ void k_scan1() {
    __shared__ int sh[256];
    int tid = threadIdx.x;
    int i = blockIdx.x * 256 + tid;
    int v = (i < NN) ? g_cnt[i] : 0;
    sh[tid] = v; __syncthreads();
    #pragma unroll
    for (int off = 1; off < 256; off <<= 1) {
        int t = (tid >= off) ? sh[tid - off] : 0;
        __syncthreads();
        sh[tid] += t;
        __syncthreads();
    }
    if (i < NN) g_tmp[i] = sh[tid] - v;
    if (tid == 255) g_bsum[blockIdx.x] = sh[255];
}

__global__ void k_scan2() {
    __shared__ int sh[256];
    int tid = threadIdx.x;
    int v = (tid < NSCB) ? g_bsum[tid] : 0;
    sh[tid] = v; __syncthreads();
    #pragma unroll
    for (int off = 1; off < 256; off <<= 1) {
        int t = (tid >= off) ? sh[tid - off] : 0;
        __syncthreads();
        sh[tid] += t;
        __syncthreads();
    }
    g_boff[tid] = sh[tid] - v;
}

__global__ void k_scan3() {
    int i = blockIdx.x * 256 + threadIdx.x;
    if (i < NN) {
        int r = g_tmp[i] + g_boff[blockIdx.x];
        g_rowptr[i] = r;
        g_pos[i] = r;
    }
    if (i == 0) g_rowptr[NN] = NE;
}

// ---------------- scatter + gate-prescale: gatep[p] = gate[e] * dis4[src] ----------------
__global__ void k_scatter(const int* __restrict__ rowp,
                          const int* __restrict__ colp) {
    int e = blockIdx.x * blockDim.x + threadIdx.x;
    if (e >= NE) return;
    int c = clampi(colp[e], NN);
    int s = clampi(rowp[e], NN);
    int p = atomicAdd(&g_pos[c], 1);
    p = clampi(p, NE);
    float4 d = g_dis4[s];               // random 16B gather
    float4 g = g_gate[e];               // sequential 16B
    g_srcp[p] = s;
    g_gatep[p] = make_float4(g.x * d.x, g.y * d.y, g.z * d.z, g.w * d.w);
}

// ---------------- SpMM (quarter-warp split): out = disc*(sum gp*h[src] + disc*h[c]) + b
__global__ __launch_bounds__(256) void k_spmm(const float* __restrict__ bias,
                                              float* __restrict__ xout,
                                              int l, int dorelu,
                                              const int* __restrict__ pick, int nrows) {
    int w = (blockIdx.x * blockDim.x + threadIdx.x) >> 5;
    int lane = threadIdx.x & 31;
    int q = lane >> 3;
    int li = lane & 7;
    if (w >= nrows) return;
    int c = pick ? clampi(pick[w], NN) : w;
    int rs = g_rowptr[c], re = g_rowptr[c + 1];
    ull a0 = 0, a1 = 0, a2 = 0, a3 = 0;
    #pragma unroll 2
    for (int p = rs + q; p < re; p += 4) {
        int s = g_srcp[p];
        float g = ((const float*)&g_gatep[p])[l];
        const ull* hp = (const ull*)&g_h[(size_t)s * HID + li * 8];
        ulonglong2 h01 = *(const ulonglong2*)hp;
        ulonglong2 h23 = *(const ulonglong2*)(hp + 2);
        ull gp = pack2(g);
        fma2(a0, gp, h01.x);
        fma2(a1, gp, h01.y);
        fma2(a2, gp, h23.x);
        fma2(a3, gp, h23.y);
    }
    float disc = ((const float*)&g_dis4[c])[l];
    {
        ull one = pack2(1.f);
        #pragma unroll
        for (int off = 8; off <= 16; off <<= 1) {
            ull t0 = __shfl_xor_sync(0xffffffffu, a0, off);
            ull t1 = __shfl_xor_sync(0xffffffffu, a1, off);
            ull t2 = __shfl_xor_sync(0xffffffffu, a2, off);
            ull t3 = __shfl_xor_sync(0xffffffffu, a3, off);
            fma2(a0, one, t0);
            fma2(a1, one, t1);
            fma2(a2, one, t2);
            fma2(a3, one, t3);
        }
        // self loop: + disc * h[c]
        ull dp = pack2(disc);
        const ull* hp = (const ull*)&g_h[(size_t)c * HID + li * 8];
        ulonglong2 h01 = *(const ulonglong2*)hp;
        ulonglong2 h23 = *(const ulonglong2*)(hp + 2);
        fma2(a0, dp, h01.x);
        fma2(a1, dp, h01.y);
        fma2(a2, dp, h23.x);
        fma2(a3, dp, h23.y);
    }
    if (q == 0) {
        float o[8];
        unpack2(a0, o[0], o[1]); unpack2(a1, o[2], o[3]);
        unpack2(a2, o[4], o[5]); unpack2(a3, o[6], o[7]);
        float4 b0 = *(const float4*)&bias[li * 8];
        float4 b1 = *(const float4*)&bias[li * 8 + 4];
        o[0] = o[0] * disc + b0.x; o[1] = o[1] * disc + b0.y;
        o[2] = o[2] * disc + b0.z; o[3] = o[3] * disc + b0.w;
        o[4] = o[4] * disc + b1.x; o[5] = o[5] * disc + b1.y;
        o[6] = o[6] * disc + b1.z; o[7] = o[7] * disc + b1.w;
        if (dorelu) {
            #pragma unroll
            for (int i = 0; i < 8; i++) o[i] = fmaxf(o[i], 0.f);
        }
        float* dst = &xout[(size_t)w * HID + li * 8];
        *(float4*)dst = make_float4(o[0], o[1], o[2], o[3]);
        *(float4*)(dst + 4) = make_float4(o[4], o[5], o[6], o[7]);
    }
}

// ---------------- classifier + softmax on compacted picked rows ----------------
__global__ __launch_bounds__(128) void k_final(const float* __restrict__ xin,
                                               const float* __restrict__ linW,
                                               const float* __restrict__ linb,
                                               float* __restrict__ out) {
    __shared__ float sW[HID * NC];
    __shared__ float sb[NC];
    for (int i = threadIdx.x; i < HID * NC; i += 128) sW[i] = linW[i];
    if (threadIdx.x < NC) sb[threadIdx.x] = linb[threadIdx.x];
    __syncthreads();
    int t = blockIdx.x * 128 + threadIdx.x;
    if (t >= NPICK) return;
    float lg[NC];
    #pragma unroll
    for (int j = 0; j < NC; j++) lg[j] = sb[j];
    const float4* xr = (const float4*)&xin[(size_t)t * HID];
    #pragma unroll
    for (int k4 = 0; k4 < 16; k4++) {
        float4 v = xr[k4];
        float xs[4] = {v.x, v.y, v.z, v.w};
        #pragma unroll
        for (int q = 0; q < 4; q++) {
            #pragma unroll
            for (int j = 0; j < NC; j++) lg[j] += xs[q] * sW[(k4 * 4 + q) * NC + j];
        }
    }
    float m = lg[0];
    #pragma unroll
    for (int j = 1; j < NC; j++) m = fmaxf(m, lg[j]);
    float ex[NC], s = 0.f;
    #pragma unroll
    for (int j = 0; j < NC; j++) { ex[j] = __expf(lg[j] - m); s += ex[j]; }
    float inv = 1.f / s;
    #pragma unroll
    for (int j = 0; j < NC; j++) out[(size_t)t * NC + j] = ex[j] * inv;
}

// ---------------- launch ----------------
extern "C" void kernel_launch(void* const* d_in, const int* in_sizes, int n_in,
                              void* d_out, int out_size) {
    const float* x      = (const float*)d_in[0];
    const float* eattr  = (const float*)d_in[1];
    const float* encW1  = (const float*)d_in[2];
    const float* encb1  = (const float*)d_in[3];
    const float* encW2  = (const float*)d_in[4];
    const float* encb2  = (const float*)d_in[5];
    const float* convW  = (const float*)d_in[6];
    const float* convB  = (const float*)d_in[7];
    const float* mlpW1  = (const float*)d_in[8];
    const float* mlpb1  = (const float*)d_in[9];
    const float* mlpW2  = (const float*)d_in[10];
    const float* mlpb2  = (const float*)d_in[11];
    const float* linW   = (const float*)d_in[12];
    const float* linb   = (const float*)d_in[13];
    const int* eidx     = (const int*)d_in[14];   // int32 (JAX x64 disabled)
    const int* pick     = (const int*)d_in[15];
    float* out = (float*)d_out;

    const int* rowp = eidx;
    const int* colp = eidx + NE;

    float *xa, *xb;
    cudaGetSymbolAddress((void**)&xa, g_xa);
    cudaGetSymbolAddress((void**)&xb, g_xb);

    const int EB = (NE + 255) / 256;        // 3125
    const int WB = (NN * 32 + 255) / 256;   // 6250
    const int PB = (NPICK * 32) / 256;      // 512

    // launch index 0..2
    k_fold<<<1, 256>>>(encW1, encb1, encW2, encb2, mlpW1, mlpb1);
    k_zero<<<(4 * NN + 255) / 256, 256>>>();
    k_count<<<EB, 256>>>(colp);

    // launch index 3: tiled gemm layer 0 (profiled by ncu window)
    k_gemm<<<GBLK, 256>>>(x, convW);

    // gates + degrees
    k_edge<<<EBLK, 256>>>(eattr, colp, mlpW2, mlpb2);
    k_dis4<<<(NN + 255) / 256, 256>>>();

    // CSR scan + scatter (scatter prescales gates by dis[src] and permutes)
    k_scan1<<<NSCB, 256>>>();
    k_scan2<<<1, 256>>>();
    k_scan3<<<NSCB, 256>>>();
    k_scatter<<<EB, 256>>>(rowp, colp);

    // layer 0 spmm, then layers 1-2, then picked layer 3
    float* bufs[2] = { xa, xb };
    k_spmm<<<WB, 256>>>(convB, bufs[0], 0, 1, (const int*)nullptr, NN);
    const float* xin = bufs[0];
    for (int l = 1; l < 3; l++) {
        k_gemm<<<GBLK, 256>>>(xin, convW + l * HID * HID);
        k_spmm<<<WB, 256>>>(convB + l * HID, bufs[l & 1], l, 1, (const int*)nullptr, NN);
        xin = bufs[l & 1];
    }
    k_gemm<<<GBLK, 256>>>(xin, convW + 3 * HID * HID);
    k_spmm<<<PB, 256>>>(convB + 3 * HID, xb, 3, 0, pick, NPICK);

    k_final<<<32, 128>>>(xb, linW, linb, out);
}